// round 3
// baseline (speedup 1.0000x reference)
#include <cuda_runtime.h>
#include <math.h>
#include <stdint.h>

// Problem constants
#define BN  32768
#define DIM 256
#define NK  32
#define NH  8
#define NFF 1024
#define NDK 32

// ---------------- scratch (device globals: allocation-guard-safe) ----------------
__device__ __align__(128) float g_lnx[BN * DIM];        // LN1(x_anc)
__device__ __align__(128) float g_q[BN * DIM];          // Q
__device__ __align__(128) float g_qt[BN * NH * DIM];    // q~ [B, H, 256]
__device__ __align__(128) float g_ctx[BN * NH * DIM];   // ctx [B, H, 256]
__device__ __align__(128) float g_att[BN * DIM];        // attention output (pre-W_o)
__device__ __align__(128) float g_x[BN * DIM];          // x = x_anc + att @ W_o
__device__ __align__(128) float g_h[BN * DIM];          // LN2(x)
__device__ __align__(128) float g_ff[BN * NFF];         // gelu(h@ff1+b1)

// ---------------- LayerNorm: one warp per row ----------------
__global__ void ln_kernel(const float* __restrict__ x, const float* __restrict__ g,
                          const float* __restrict__ b, float* __restrict__ out) {
    int row  = blockIdx.x * 8 + threadIdx.y;
    int lane = threadIdx.x;
    const float4* xr = reinterpret_cast<const float4*>(x + (size_t)row * DIM);
    float4 v0 = xr[lane];
    float4 v1 = xr[lane + 32];
    float s  = v0.x + v0.y + v0.z + v0.w + v1.x + v1.y + v1.z + v1.w;
    float ss = v0.x*v0.x + v0.y*v0.y + v0.z*v0.z + v0.w*v0.w
             + v1.x*v1.x + v1.y*v1.y + v1.z*v1.z + v1.w*v1.w;
    #pragma unroll
    for (int o = 16; o; o >>= 1) {
        s  += __shfl_xor_sync(0xFFFFFFFFu, s,  o);
        ss += __shfl_xor_sync(0xFFFFFFFFu, ss, o);
    }
    float mu  = s * (1.0f / 256.0f);
    float var = ss * (1.0f / 256.0f) - mu * mu;
    float rs  = rsqrtf(var + 1e-5f);
    const float4* g4 = reinterpret_cast<const float4*>(g);
    const float4* b4 = reinterpret_cast<const float4*>(b);
    float4* orow = reinterpret_cast<float4*>(out + (size_t)row * DIM);
    #pragma unroll
    for (int p = 0; p < 2; p++) {
        int idx = lane + p * 32;
        float4 v = (p == 0) ? v0 : v1;
        float4 gg = g4[idx], bb = b4[idx];
        float4 o4;
        o4.x = (v.x - mu) * rs * gg.x + bb.x;
        o4.y = (v.y - mu) * rs * gg.y + bb.y;
        o4.z = (v.z - mu) * rs * gg.z + bb.z;
        o4.w = (v.w - mu) * rs * gg.w + bb.w;
        orow[idx] = o4;
    }
}

__device__ __forceinline__ float gelu_exact(float v) {
    return 0.5f * v * (1.0f + erff(v * 0.70710678118654752f));
}

// ---------------- cp.async helpers ----------------
__device__ __forceinline__ void cp_async16(float* smem_ptr, const float* gptr) {
    uint32_t sa = (uint32_t)__cvta_generic_to_shared(smem_ptr);
    asm volatile("cp.async.cg.shared.global [%0], [%1], 16;\n" :: "r"(sa), "l"(gptr));
}
__device__ __forceinline__ void cp_commit() {
    asm volatile("cp.async.commit_group;\n" ::: "memory");
}
__device__ __forceinline__ void cp_wait0() {
    asm volatile("cp.async.wait_group 0;\n" ::: "memory");
}

// ---------------- tf32 tensor-core GEMM: 128x128x32 tiles, cp.async pipeline ----------------
// MODE 0: C = A@B
// MODE 1: C = gelu(A@B + bias)
// MODE 2: C = A@B + bias + resid
// MODE 3: C = A@B + resid
__device__ __forceinline__ void mma_tf32(float c[4], const uint32_t a[4], const uint32_t b[2]) {
    asm volatile(
        "mma.sync.aligned.m16n8k8.row.col.f32.tf32.tf32.f32 "
        "{%0,%1,%2,%3}, {%4,%5,%6,%7}, {%8,%9}, {%0,%1,%2,%3};\n"
        : "+f"(c[0]), "+f"(c[1]), "+f"(c[2]), "+f"(c[3])
        : "r"(a[0]), "r"(a[1]), "r"(a[2]), "r"(a[3]), "r"(b[0]), "r"(b[1]));
}

#define AS_STRIDE 36
#define BS_STRIDE 132
#define AS_BUF (128 * AS_STRIDE)
#define BS_BUF (32 * BS_STRIDE)
#define TGEMM_SMEM ((2 * AS_BUF + 2 * BS_BUF) * 4)

template <int MODE>
__global__ __launch_bounds__(256, 2)
void tgemm(const float* __restrict__ A, const float* __restrict__ Bw,
           float* __restrict__ C, int M, int N, int Kd,
           const float* __restrict__ bias, const float* __restrict__ resid) {
    extern __shared__ float sm[];
    float* As = sm;                 // [2][128][36]
    float* Bs = sm + 2 * AS_BUF;    // [2][32][132]

    const int tid  = threadIdx.x;
    const int lane = tid & 31;
    const int wid  = tid >> 5;
    const int m0 = blockIdx.y * 128;
    const int n0 = blockIdx.x * 128;
    const int warp_m = (wid & 1) * 64;
    const int warp_n = (wid >> 1) * 32;

    // cp.async tile-load assignments
    const int aRow = tid >> 1;            // 0..127 (each thread: 16 floats of one A row)
    const int aCol = (tid & 1) * 16;      // 0 or 16
    const int bRow = tid >> 3;            // 0..31 (each thread: 16 floats of one B row)
    const int bCol = (tid & 7) * 16;      // 0..112

    const float* Ag = A  + (size_t)(m0 + aRow) * Kd + aCol;
    const float* Bg = Bw + (size_t)bRow * N + n0 + bCol;

    float c[4][4][4];
    #pragma unroll
    for (int mt = 0; mt < 4; mt++)
        #pragma unroll
        for (int nt = 0; nt < 4; nt++)
            #pragma unroll
            for (int i = 0; i < 4; i++) c[mt][nt][i] = 0.0f;

    // prologue: async-load k-tile 0 into buffer 0
    {
        float* Ad = As + aRow * AS_STRIDE + aCol;
        const float* Asrc = Ag;
        cp_async16(Ad + 0,  Asrc + 0);
        cp_async16(Ad + 4,  Asrc + 4);
        cp_async16(Ad + 8,  Asrc + 8);
        cp_async16(Ad + 12, Asrc + 12);
        float* Bd = Bs + bRow * BS_STRIDE + bCol;
        const float* Bsrc = Bg;
        cp_async16(Bd + 0,  Bsrc + 0);
        cp_async16(Bd + 4,  Bsrc + 4);
        cp_async16(Bd + 8,  Bsrc + 8);
        cp_async16(Bd + 12, Bsrc + 12);
        cp_commit();
    }
    cp_wait0();
    __syncthreads();

    const int KT = Kd >> 5;
    int buf = 0;
    const int fr = lane >> 2;     // 0..7
    const int fc = lane & 3;      // 0..3

    for (int kt = 0; kt < KT; kt++) {
        if (kt + 1 < KT) {
            int nb = buf ^ 1;
            float* Ad = As + nb * AS_BUF + aRow * AS_STRIDE + aCol;
            const float* Asrc = Ag + (kt + 1) * 32;
            cp_async16(Ad + 0,  Asrc + 0);
            cp_async16(Ad + 4,  Asrc + 4);
            cp_async16(Ad + 8,  Asrc + 8);
            cp_async16(Ad + 12, Asrc + 12);
            float* Bd = Bs + nb * BS_BUF + bRow * BS_STRIDE + bCol;
            const float* Bsrc = Bg + (size_t)(kt + 1) * 32 * N;
            cp_async16(Bd + 0,  Bsrc + 0);
            cp_async16(Bd + 4,  Bsrc + 4);
            cp_async16(Bd + 8,  Bsrc + 8);
            cp_async16(Bd + 12, Bsrc + 12);
            cp_commit();
        }

        const float* Ab = As + buf * AS_BUF;
        const float* Bb = Bs + buf * BS_BUF;
        #pragma unroll
        for (int ks = 0; ks < 32; ks += 8) {
            uint32_t af[4][4];
            uint32_t bf[4][2];
            #pragma unroll
            for (int mt = 0; mt < 4; mt++) {
                int r = warp_m + mt * 16 + fr;
                af[mt][0] = __float_as_uint(Ab[r * AS_STRIDE + ks + fc]);
                af[mt][1] = __float_as_uint(Ab[(r + 8) * AS_STRIDE + ks + fc]);
                af[mt][2] = __float_as_uint(Ab[r * AS_STRIDE + ks + fc + 4]);
                af[mt][3] = __float_as_uint(Ab[(r + 8) * AS_STRIDE + ks + fc + 4]);
            }
            #pragma unroll
            for (int nt = 0; nt < 4; nt++) {
                int cn = warp_n + nt * 8 + fr;
                bf[nt][0] = __float_as_uint(Bb[(ks + fc) * BS_STRIDE + cn]);
                bf[nt][1] = __float_as_uint(Bb[(ks + 4 + fc) * BS_STRIDE + cn]);
            }
            #pragma unroll
            for (int mt = 0; mt < 4; mt++)
                #pragma unroll
                for (int nt = 0; nt < 4; nt++)
                    mma_tf32(c[mt][nt], af[mt], bf[nt]);
        }

        if (kt + 1 < KT) cp_wait0();
        __syncthreads();
        buf ^= 1;
    }

    // epilogue
    #pragma unroll
    for (int mt = 0; mt < 4; mt++) {
        #pragma unroll
        for (int nt = 0; nt < 4; nt++) {
            int row0 = m0 + warp_m + mt * 16 + fr;
            int col  = n0 + warp_n + nt * 8 + fc * 2;
            float v0 = c[mt][nt][0], v1 = c[mt][nt][1];
            float v2 = c[mt][nt][2], v3 = c[mt][nt][3];
            if (MODE == 1 || MODE == 2) {
                float2 bv = *reinterpret_cast<const float2*>(bias + col);
                v0 += bv.x; v1 += bv.y; v2 += bv.x; v3 += bv.y;
            }
            if (MODE == 1) {
                v0 = gelu_exact(v0); v1 = gelu_exact(v1);
                v2 = gelu_exact(v2); v3 = gelu_exact(v3);
            }
            if (MODE == 2 || MODE == 3) {
                float2 r0 = *reinterpret_cast<const float2*>(resid + (size_t)row0 * N + col);
                float2 r1 = *reinterpret_cast<const float2*>(resid + (size_t)(row0 + 8) * N + col);
                v0 += r0.x; v1 += r0.y; v2 += r1.x; v3 += r1.y;
            }
            float2 o0 = make_float2(v0, v1);
            float2 o1 = make_float2(v2, v3);
            *reinterpret_cast<float2*>(C + (size_t)row0 * N + col)       = o0;
            *reinterpret_cast<float2*>(C + (size_t)(row0 + 8) * N + col) = o1;
        }
    }
}

// ---------------- q~[b,h,d] = sum_j Q[b, h*32+j] * W_k[d, h*32+j] ----------------
__global__ void qtilde_kernel(const float* __restrict__ Q, const float* __restrict__ Wk,
                              float* __restrict__ qt) {
    __shared__ float Wks[256 * 33];
    __shared__ float Qs[8 * 32];
    int h  = blockIdx.y;
    int b0 = blockIdx.x * 8;
    int tid = threadIdx.x;
    for (int i = tid; i < 8192; i += 256) {
        int d = i >> 5, j = i & 31;
        Wks[d * 33 + j] = Wk[d * 256 + h * 32 + j];
    }
    {
        int r = tid >> 5, j = tid & 31;
        Qs[tid] = Q[(size_t)(b0 + r) * 256 + h * 32 + j];
    }
    __syncthreads();
    int d = tid;
    float w[32];
    #pragma unroll
    for (int j = 0; j < 32; j++) w[j] = Wks[d * 33 + j];
    float acc[8];
    #pragma unroll
    for (int r = 0; r < 8; r++) acc[r] = 0.0f;
    const float4* Qs4 = reinterpret_cast<const float4*>(Qs);
    #pragma unroll
    for (int r = 0; r < 8; r++) {
        #pragma unroll
        for (int j4 = 0; j4 < 8; j4++) {
            float4 q = Qs4[r * 8 + j4];
            acc[r] += q.x * w[j4 * 4 + 0] + q.y * w[j4 * 4 + 1]
                    + q.z * w[j4 * 4 + 2] + q.w * w[j4 * 4 + 3];
        }
    }
    #pragma unroll
    for (int r = 0; r < 8; r++)
        qt[(size_t)(b0 + r) * 2048 + h * 256 + d] = acc[r];
}

// ---------------- attention core v3, one block per anchor b ----------------
// Phase1: warp = (4-head group, d-quarter); lane = k; q read via broadcast LDG.
// Phase2: warp = (4-head group, d-quarter); lane = d-pair; x float2 feeds 4 heads.
__global__ __launch_bounds__(256)
void attn_kernel(const float* __restrict__ xnei, const float* __restrict__ qt,
                 float* __restrict__ ctx) {
    __shared__ float xs[32 * 260];   // padded: conflict-free float4 (phase1) & float2 (phase2)
    __shared__ float sred[4 * 8 * 32];
    __shared__ float attns[8 * 32];
    int b    = blockIdx.x;
    int tid  = threadIdx.x;
    int lane = tid & 31;
    int w    = tid >> 5;

    const float4* xb4 = reinterpret_cast<const float4*>(xnei + (size_t)b * 8192);
    #pragma unroll
    for (int j = 0; j < 8; j++) {
        int i  = tid + j * 256;
        int k  = i >> 6;
        int c4 = i & 63;
        *reinterpret_cast<float4*>(xs + k * 260 + c4 * 4) = xb4[i];
    }
    __syncthreads();

    int hg  = w >> 2;   // head group: heads hg*4 .. hg*4+3
    int dqt = w & 3;    // d-quarter

    // ---- phase 1: partial scores (lane = k) ----
    {
        int k = lane;
        float s0 = 0.f, s1 = 0.f, s2 = 0.f, s3 = 0.f;
        const float*  xr = xs + k * 260 + dqt * 64;
        const float* qb = qt + (size_t)b * 2048;
        const float4* q0 = reinterpret_cast<const float4*>(qb + (hg * 4 + 0) * 256) + dqt * 16;
        const float4* q1 = reinterpret_cast<const float4*>(qb + (hg * 4 + 1) * 256) + dqt * 16;
        const float4* q2 = reinterpret_cast<const float4*>(qb + (hg * 4 + 2) * 256) + dqt * 16;
        const float4* q3 = reinterpret_cast<const float4*>(qb + (hg * 4 + 3) * 256) + dqt * 16;
        #pragma unroll
        for (int d4 = 0; d4 < 16; d4++) {
            float4 xv = *reinterpret_cast<const float4*>(xr + d4 * 4);
            float4 qa = q0[d4], qb4 = q1[d4], qc = q2[d4], qd = q3[d4];
            s0 = fmaf(qa.x,  xv.x, fmaf(qa.y,  xv.y, fmaf(qa.z,  xv.z, fmaf(qa.w,  xv.w, s0))));
            s1 = fmaf(qb4.x, xv.x, fmaf(qb4.y, xv.y, fmaf(qb4.z, xv.z, fmaf(qb4.w, xv.w, s1))));
            s2 = fmaf(qc.x,  xv.x, fmaf(qc.y,  xv.y, fmaf(qc.z,  xv.z, fmaf(qc.w,  xv.w, s2))));
            s3 = fmaf(qd.x,  xv.x, fmaf(qd.y,  xv.y, fmaf(qd.z,  xv.z, fmaf(qd.w,  xv.w, s3))));
        }
        sred[dqt * 256 + (hg * 4 + 0) * 32 + k] = s0;
        sred[dqt * 256 + (hg * 4 + 1) * 32 + k] = s1;
        sred[dqt * 256 + (hg * 4 + 2) * 32 + k] = s2;
        sred[dqt * 256 + (hg * 4 + 3) * 32 + k] = s3;
    }
    __syncthreads();

    // ---- softmax: warp w handles head h=w ----
    {
        int h = w, k = lane;
        float sc = (sred[0 * 256 + h * 32 + k] + sred[1 * 256 + h * 32 + k]
                  + sred[2 * 256 + h * 32 + k] + sred[3 * 256 + h * 32 + k])
                 * 0.17677669529663687f;   // 1/sqrt(32)
        float m = sc;
        #pragma unroll
        for (int o = 16; o; o >>= 1) m = fmaxf(m, __shfl_xor_sync(0xFFFFFFFFu, m, o));
        float e = expf(sc - m);
        float s = e;
        #pragma unroll
        for (int o = 16; o; o >>= 1) s += __shfl_xor_sync(0xFFFFFFFFu, s, o);
        attns[h * 32 + k] = e / s;
    }
    __syncthreads();

    // ---- phase 2: ctx (lane = d-pair; one x float2 feeds 4 heads) ----
    {
        int dbase = dqt * 64 + lane * 2;
        float acc[4][2];
        #pragma unroll
        for (int h = 0; h < 4; h++) { acc[h][0] = 0.f; acc[h][1] = 0.f; }
        #pragma unroll
        for (int k0 = 0; k0 < 32; k0 += 4) {
            float4 a0 = *reinterpret_cast<const float4*>(&attns[(hg * 4 + 0) * 32 + k0]);
            float4 a1 = *reinterpret_cast<const float4*>(&attns[(hg * 4 + 1) * 32 + k0]);
            float4 a2 = *reinterpret_cast<const float4*>(&attns[(hg * 4 + 2) * 32 + k0]);
            float4 a3 = *reinterpret_cast<const float4*>(&attns[(hg * 4 + 3) * 32 + k0]);
            float av0[4] = {a0.x, a0.y, a0.z, a0.w};
            float av1[4] = {a1.x, a1.y, a1.z, a1.w};
            float av2[4] = {a2.x, a2.y, a2.z, a2.w};
            float av3[4] = {a3.x, a3.y, a3.z, a3.w};
            #pragma unroll
            for (int kk = 0; kk < 4; kk++) {
                float2 xv = *reinterpret_cast<const float2*>(xs + (k0 + kk) * 260 + dbase);
                acc[0][0] = fmaf(av0[kk], xv.x, acc[0][0]);
                acc[0][1] = fmaf(av0[kk], xv.y, acc[0][1]);
                acc[1][0] = fmaf(av1[kk], xv.x, acc[1][0]);
                acc[1][1] = fmaf(av1[kk], xv.y, acc[1][1]);
                acc[2][0] = fmaf(av2[kk], xv.x, acc[2][0]);
                acc[2][1] = fmaf(av2[kk], xv.y, acc[2][1]);
                acc[3][0] = fmaf(av3[kk], xv.x, acc[3][0]);
                acc[3][1] = fmaf(av3[kk], xv.y, acc[3][1]);
            }
        }
        float* cb = ctx + (size_t)b * 2048;
        #pragma unroll
        for (int h = 0; h < 4; h++) {
            *reinterpret_cast<float2*>(cb + (hg * 4 + h) * 256 + dbase) =
                make_float2(acc[h][0], acc[h][1]);
        }
    }
}

// ---------------- out[b, h*32+j] = sum_d ctx[b,h,d] * W_v[d, h*32+j] ----------------
__global__ void vproj_kernel(const float* __restrict__ ctx, const float* __restrict__ Wv,
                             float* __restrict__ out) {
    __shared__ float Wvs[256 * 32];
    __shared__ float cs[16 * 256];
    int h  = blockIdx.y;
    int b0 = blockIdx.x * 16;
    int tid = threadIdx.x;
    for (int i = tid * 4; i < 8192; i += 1024) {
        int d = i >> 5, j = i & 31;
        *reinterpret_cast<float4*>(&Wvs[i]) =
            *reinterpret_cast<const float4*>(&Wv[d * 256 + h * 32 + j]);
    }
    for (int i = tid * 4; i < 4096; i += 1024) {
        int r = i >> 8, d2 = i & 255;
        *reinterpret_cast<float4*>(&cs[i]) =
            *reinterpret_cast<const float4*>(&ctx[(size_t)(b0 + r) * 2048 + h * 256 + d2]);
    }
    __syncthreads();
    int j  = tid & 31;
    int rg = tid >> 5;
    float acc0 = 0.0f, acc1 = 0.0f;
    #pragma unroll 4
    for (int d4 = 0; d4 < 64; d4++) {
        float w0 = Wvs[(d4 * 4 + 0) * 32 + j];
        float w1 = Wvs[(d4 * 4 + 1) * 32 + j];
        float w2 = Wvs[(d4 * 4 + 2) * 32 + j];
        float w3 = Wvs[(d4 * 4 + 3) * 32 + j];
        float4 c0 = *reinterpret_cast<const float4*>(&cs[rg * 256 + d4 * 4]);
        float4 c1 = *reinterpret_cast<const float4*>(&cs[(rg + 8) * 256 + d4 * 4]);
        acc0 += c0.x * w0 + c0.y * w1 + c0.z * w2 + c0.w * w3;
        acc1 += c1.x * w0 + c1.y * w1 + c1.z * w2 + c1.w * w3;
    }
    out[(size_t)(b0 + rg) * 256 + h * 32 + j]     = acc0;
    out[(size_t)(b0 + rg + 8) * 256 + h * 32 + j] = acc1;
}

// ---------------- launcher ----------------
extern "C" void kernel_launch(void* const* d_in, const int* in_sizes, int n_in,
                              void* d_out, int out_size) {
    const float* x_anc = (const float*)d_in[0];
    const float* x_nei = (const float*)d_in[1];
    const float* W_q   = (const float*)d_in[2];
    const float* W_k   = (const float*)d_in[3];
    const float* W_v   = (const float*)d_in[4];
    const float* W_o   = (const float*)d_in[5];
    const float* ln1_g = (const float*)d_in[6];
    const float* ln1_b = (const float*)d_in[7];
    const float* ln2_g = (const float*)d_in[8];
    const float* ln2_b = (const float*)d_in[9];
    const float* ff1_w = (const float*)d_in[10];
    const float* ff1_b = (const float*)d_in[11];
    const float* ff2_w = (const float*)d_in[12];
    const float* ff2_b = (const float*)d_in[13];
    float* out = (float*)d_out;

    float *p_lnx, *p_q, *p_qt, *p_ctx, *p_att, *p_x, *p_h, *p_ff;
    cudaGetSymbolAddress((void**)&p_lnx, g_lnx);
    cudaGetSymbolAddress((void**)&p_q,   g_q);
    cudaGetSymbolAddress((void**)&p_qt,  g_qt);
    cudaGetSymbolAddress((void**)&p_ctx, g_ctx);
    cudaGetSymbolAddress((void**)&p_att, g_att);
    cudaGetSymbolAddress((void**)&p_x,   g_x);
    cudaGetSymbolAddress((void**)&p_h,   g_h);
    cudaGetSymbolAddress((void**)&p_ff,  g_ff);

    // opt-in to 69KB dynamic smem for the GEMMs (host-side, capture-safe)
    cudaFuncSetAttribute(tgemm<0>, cudaFuncAttributeMaxDynamicSharedMemorySize, TGEMM_SMEM);
    cudaFuncSetAttribute(tgemm<1>, cudaFuncAttributeMaxDynamicSharedMemorySize, TGEMM_SMEM);
    cudaFuncSetAttribute(tgemm<2>, cudaFuncAttributeMaxDynamicSharedMemorySize, TGEMM_SMEM);
    cudaFuncSetAttribute(tgemm<3>, cudaFuncAttributeMaxDynamicSharedMemorySize, TGEMM_SMEM);

    dim3 lnBlock(32, 8);

    // 1. LN1
    ln_kernel<<<BN / 8, lnBlock>>>(x_anc, ln1_g, ln1_b, p_lnx);
    // 2. Q = LN1 @ W_q  (tf32 tensor cores)
    tgemm<0><<<dim3(DIM / 128, BN / 128), 256, TGEMM_SMEM>>>(p_lnx, W_q, p_q, BN, DIM, DIM, nullptr, nullptr);
    // 3. q~ per head
    qtilde_kernel<<<dim3(BN / 8, NH), 256>>>(p_q, W_k, p_qt);
    // 4. attention core -> ctx
    attn_kernel<<<BN, 256>>>(x_nei, p_qt, p_ctx);
    // 5. out = ctx @ W_v (per head)
    vproj_kernel<<<dim3(BN / 16, NH), 256>>>(p_ctx, W_v, p_att);
    // 6. x = x_anc + att @ W_o
    tgemm<3><<<dim3(DIM / 128, BN / 128), 256, TGEMM_SMEM>>>(p_att, W_o, p_x, BN, DIM, DIM, nullptr, x_anc);
    // 7. LN2
    ln_kernel<<<BN / 8, lnBlock>>>(p_x, ln2_g, ln2_b, p_h);
    // 8. ff = gelu(h @ ff1 + b1)
    tgemm<1><<<dim3(NFF / 128, BN / 128), 256, TGEMM_SMEM>>>(p_h, ff1_w, p_ff, BN, NFF, DIM, ff1_b, nullptr);
    // 9. out = x + ff @ ff2 + b2
    tgemm<2><<<dim3(DIM / 128, BN / 128), 256, TGEMM_SMEM>>>(p_ff, ff2_w, out, BN, DIM, NFF, ff2_b, p_x);
}

// round 4
// speedup vs baseline: 1.1202x; 1.1202x over previous
#include <cuda_runtime.h>
#include <math.h>
#include <stdint.h>

// Problem constants
#define BN  32768
#define DIM 256
#define NK  32
#define NH  8
#define NFF 1024
#define NDK 32

// ---------------- scratch (device globals: allocation-guard-safe) ----------------
__device__ __align__(128) float g_lnx[BN * DIM];        // LN1(x_anc)
__device__ __align__(128) float g_q[BN * DIM];          // Q
__device__ __align__(128) float g_qt[BN * NH * DIM];    // q~ [B, H, 256]
__device__ __align__(128) float g_ctx[BN * NH * DIM];   // ctx [B, H, 256]
__device__ __align__(128) float g_att[BN * DIM];        // attention output (pre-W_o)
__device__ __align__(128) float g_x[BN * DIM];          // x = x_anc + att @ W_o
__device__ __align__(128) float g_h[BN * DIM];          // LN2(x)
__device__ __align__(128) float g_ff[BN * NFF];         // gelu(h@ff1+b1)

// ---------------- LayerNorm: one warp per row ----------------
__global__ void ln_kernel(const float* __restrict__ x, const float* __restrict__ g,
                          const float* __restrict__ b, float* __restrict__ out) {
    int row  = blockIdx.x * 8 + threadIdx.y;
    int lane = threadIdx.x;
    const float4* xr = reinterpret_cast<const float4*>(x + (size_t)row * DIM);
    float4 v0 = xr[lane];
    float4 v1 = xr[lane + 32];
    float s  = v0.x + v0.y + v0.z + v0.w + v1.x + v1.y + v1.z + v1.w;
    float ss = v0.x*v0.x + v0.y*v0.y + v0.z*v0.z + v0.w*v0.w
             + v1.x*v1.x + v1.y*v1.y + v1.z*v1.z + v1.w*v1.w;
    #pragma unroll
    for (int o = 16; o; o >>= 1) {
        s  += __shfl_xor_sync(0xFFFFFFFFu, s,  o);
        ss += __shfl_xor_sync(0xFFFFFFFFu, ss, o);
    }
    float mu  = s * (1.0f / 256.0f);
    float var = ss * (1.0f / 256.0f) - mu * mu;
    float rs  = rsqrtf(var + 1e-5f);
    const float4* g4 = reinterpret_cast<const float4*>(g);
    const float4* b4 = reinterpret_cast<const float4*>(b);
    float4* orow = reinterpret_cast<float4*>(out + (size_t)row * DIM);
    #pragma unroll
    for (int p = 0; p < 2; p++) {
        int idx = lane + p * 32;
        float4 v = (p == 0) ? v0 : v1;
        float4 gg = g4[idx], bb = b4[idx];
        float4 o4;
        o4.x = (v.x - mu) * rs * gg.x + bb.x;
        o4.y = (v.y - mu) * rs * gg.y + bb.y;
        o4.z = (v.z - mu) * rs * gg.z + bb.z;
        o4.w = (v.w - mu) * rs * gg.w + bb.w;
        orow[idx] = o4;
    }
}

__device__ __forceinline__ float gelu_exact(float v) {
    return 0.5f * v * (1.0f + erff(v * 0.70710678118654752f));
}

// ---------------- tf32 tensor-core GEMM: 128x128x16 tiles (R2 version) ----------------
// MODE 0: C = A@B
// MODE 1: C = gelu(A@B + bias)
// MODE 2: C = A@B + bias + resid
// MODE 3: C = A@B + resid
__device__ __forceinline__ void mma_tf32(float c[4], const uint32_t a[4], const uint32_t b[2]) {
    asm volatile(
        "mma.sync.aligned.m16n8k8.row.col.f32.tf32.tf32.f32 "
        "{%0,%1,%2,%3}, {%4,%5,%6,%7}, {%8,%9}, {%0,%1,%2,%3};\n"
        : "+f"(c[0]), "+f"(c[1]), "+f"(c[2]), "+f"(c[3])
        : "r"(a[0]), "r"(a[1]), "r"(a[2]), "r"(a[3]), "r"(b[0]), "r"(b[1]));
}

template <int MODE>
__global__ __launch_bounds__(256, 2)
void tgemm(const float* __restrict__ A, const float* __restrict__ Bw,
           float* __restrict__ C, int M, int N, int Kd,
           const float* __restrict__ bias, const float* __restrict__ resid) {
    __shared__ float As[2][128][20];   // [buf][m][k], padded stride 20: conflict-free frag loads
    __shared__ float Bs[2][16][136];   // [buf][k][n], padded stride 136: conflict-free frag loads

    const int tid  = threadIdx.x;
    const int lane = tid & 31;
    const int wid  = tid >> 5;
    const int m0 = blockIdx.y * 128;
    const int n0 = blockIdx.x * 128;
    const int warp_m = (wid & 1) * 64;
    const int warp_n = (wid >> 1) * 32;

    // global-load assignments
    const int aRow = tid >> 1;            // 0..127
    const int aCol = (tid & 1) * 8;       // 0 or 8
    const int bRow = tid >> 4;            // 0..15
    const int bCol = (tid & 15) * 4;      // 0..60

    const float* Ag = A  + (size_t)(m0 + aRow) * Kd + aCol;
    const float* Bg = Bw + (size_t)bRow * N + n0 + bCol;

    float c[4][4][4];
    #pragma unroll
    for (int mt = 0; mt < 4; mt++)
        #pragma unroll
        for (int nt = 0; nt < 4; nt++)
            #pragma unroll
            for (int i = 0; i < 4; i++) c[mt][nt][i] = 0.0f;

    // prologue: load k-tile 0 into buffer 0
    float4 a0 = *reinterpret_cast<const float4*>(Ag);
    float4 a1 = *reinterpret_cast<const float4*>(Ag + 4);
    float4 b0 = *reinterpret_cast<const float4*>(Bg);
    float4 b1 = *reinterpret_cast<const float4*>(Bg + 64);
    *reinterpret_cast<float4*>(&As[0][aRow][aCol])     = a0;
    *reinterpret_cast<float4*>(&As[0][aRow][aCol + 4]) = a1;
    *reinterpret_cast<float4*>(&Bs[0][bRow][bCol])     = b0;
    *reinterpret_cast<float4*>(&Bs[0][bRow][bCol + 64])= b1;
    __syncthreads();

    const int KT = Kd >> 4;
    int buf = 0;
    for (int kt = 0; kt < KT; kt++) {
        if (kt + 1 < KT) {
            const float* Ap = Ag + (kt + 1) * 16;
            const float* Bp = Bg + (size_t)(kt + 1) * 16 * N;
            a0 = *reinterpret_cast<const float4*>(Ap);
            a1 = *reinterpret_cast<const float4*>(Ap + 4);
            b0 = *reinterpret_cast<const float4*>(Bp);
            b1 = *reinterpret_cast<const float4*>(Bp + 64);
        }
        #pragma unroll
        for (int ks = 0; ks < 16; ks += 8) {
            uint32_t af[4][4];
            uint32_t bf[4][2];
            const int fr = lane >> 2;     // 0..7
            const int fc = lane & 3;      // 0..3
            #pragma unroll
            for (int mt = 0; mt < 4; mt++) {
                int r = warp_m + mt * 16 + fr;
                af[mt][0] = __float_as_uint(As[buf][r][ks + fc]);
                af[mt][1] = __float_as_uint(As[buf][r + 8][ks + fc]);
                af[mt][2] = __float_as_uint(As[buf][r][ks + fc + 4]);
                af[mt][3] = __float_as_uint(As[buf][r + 8][ks + fc + 4]);
            }
            #pragma unroll
            for (int nt = 0; nt < 4; nt++) {
                int cn = warp_n + nt * 8 + fr;
                bf[nt][0] = __float_as_uint(Bs[buf][ks + fc][cn]);
                bf[nt][1] = __float_as_uint(Bs[buf][ks + 4 + fc][cn]);
            }
            #pragma unroll
            for (int mt = 0; mt < 4; mt++)
                #pragma unroll
                for (int nt = 0; nt < 4; nt++)
                    mma_tf32(c[mt][nt], af[mt], bf[nt]);
        }
        if (kt + 1 < KT) {
            buf ^= 1;
            *reinterpret_cast<float4*>(&As[buf][aRow][aCol])      = a0;
            *reinterpret_cast<float4*>(&As[buf][aRow][aCol + 4])  = a1;
            *reinterpret_cast<float4*>(&Bs[buf][bRow][bCol])      = b0;
            *reinterpret_cast<float4*>(&Bs[buf][bRow][bCol + 64]) = b1;
        }
        __syncthreads();
    }

    // epilogue
    const int fr = lane >> 2;
    const int fc = lane & 3;
    #pragma unroll
    for (int mt = 0; mt < 4; mt++) {
        #pragma unroll
        for (int nt = 0; nt < 4; nt++) {
            int row0 = m0 + warp_m + mt * 16 + fr;
            int col  = n0 + warp_n + nt * 8 + fc * 2;
            float v0 = c[mt][nt][0], v1 = c[mt][nt][1];
            float v2 = c[mt][nt][2], v3 = c[mt][nt][3];
            if (MODE == 1 || MODE == 2) {
                float2 bv = *reinterpret_cast<const float2*>(bias + col);
                v0 += bv.x; v1 += bv.y; v2 += bv.x; v3 += bv.y;
            }
            if (MODE == 1) {
                v0 = gelu_exact(v0); v1 = gelu_exact(v1);
                v2 = gelu_exact(v2); v3 = gelu_exact(v3);
            }
            if (MODE == 2 || MODE == 3) {
                float2 r0 = *reinterpret_cast<const float2*>(resid + (size_t)row0 * N + col);
                float2 r1 = *reinterpret_cast<const float2*>(resid + (size_t)(row0 + 8) * N + col);
                v0 += r0.x; v1 += r0.y; v2 += r1.x; v3 += r1.y;
            }
            float2 o0 = make_float2(v0, v1);
            float2 o1 = make_float2(v2, v3);
            *reinterpret_cast<float2*>(C + (size_t)row0 * N + col)       = o0;
            *reinterpret_cast<float2*>(C + (size_t)(row0 + 8) * N + col) = o1;
        }
    }
}

// ---------------- q~[b,h,d] = sum_j Q[b, h*32+j] * W_k[d, h*32+j] ----------------
__global__ void qtilde_kernel(const float* __restrict__ Q, const float* __restrict__ Wk,
                              float* __restrict__ qt) {
    __shared__ float Wks[256 * 33];
    __shared__ float Qs[8 * 32];
    int h  = blockIdx.y;
    int b0 = blockIdx.x * 8;
    int tid = threadIdx.x;
    for (int i = tid; i < 8192; i += 256) {
        int d = i >> 5, j = i & 31;
        Wks[d * 33 + j] = Wk[d * 256 + h * 32 + j];
    }
    {
        int r = tid >> 5, j = tid & 31;
        Qs[tid] = Q[(size_t)(b0 + r) * 256 + h * 32 + j];
    }
    __syncthreads();
    int d = tid;
    float w[32];
    #pragma unroll
    for (int j = 0; j < 32; j++) w[j] = Wks[d * 33 + j];
    float acc[8];
    #pragma unroll
    for (int r = 0; r < 8; r++) acc[r] = 0.0f;
    const float4* Qs4 = reinterpret_cast<const float4*>(Qs);
    #pragma unroll
    for (int r = 0; r < 8; r++) {
        #pragma unroll
        for (int j4 = 0; j4 < 8; j4++) {
            float4 q = Qs4[r * 8 + j4];
            acc[r] += q.x * w[j4 * 4 + 0] + q.y * w[j4 * 4 + 1]
                    + q.z * w[j4 * 4 + 2] + q.w * w[j4 * 4 + 3];
        }
    }
    #pragma unroll
    for (int r = 0; r < 8; r++)
        qt[(size_t)(b0 + r) * 2048 + h * 256 + d] = acc[r];
}

// ---------------- attention core v4, one block per anchor b ----------------
// Phase1: warp = d-eighth x all 8 heads (x float4 feeds 8 dot chains; q smem broadcast).
// Phase2: warp = (4-head group, d-quarter); x float2 feeds 4 heads.
__global__ __launch_bounds__(256)
void attn_kernel(const float* __restrict__ xnei, const float* __restrict__ qt,
                 float* __restrict__ ctx) {
    __shared__ float xs[32 * 260];   // stride 260: conflict-free float4/float2 row access
    __shared__ float qts[8 * 260];   // stride 260: conflict-free broadcasts
    __shared__ float sred[8 * 256];  // [w-slice][h*32+k]
    __shared__ float attns[8 * 32];
    int b    = blockIdx.x;
    int tid  = threadIdx.x;
    int lane = tid & 31;
    int w    = tid >> 5;

    // stage x_nei[b] : 32 x 256 floats
    const float4* xb4 = reinterpret_cast<const float4*>(xnei + (size_t)b * 8192);
    #pragma unroll
    for (int j = 0; j < 8; j++) {
        int i  = tid + j * 256;
        int k  = i >> 6;
        int c4 = i & 63;
        *reinterpret_cast<float4*>(xs + k * 260 + c4 * 4) = xb4[i];
    }
    // stage q~[b] : 8 x 256 floats into padded rows
    const float4* qrow = reinterpret_cast<const float4*>(qt + (size_t)b * 2048);
    #pragma unroll
    for (int j = 0; j < 2; j++) {
        int i  = tid + j * 256;       // 0..511
        int h  = i >> 6;
        int d4 = i & 63;
        *reinterpret_cast<float4*>(qts + h * 260 + d4 * 4) = qrow[i];
    }
    __syncthreads();

    // ---- phase 1: warp w covers d in [w*32, w*32+32), lane = k, 8 head partials ----
    {
        int k = lane;
        float acc[8];
        #pragma unroll
        for (int h = 0; h < 8; h++) acc[h] = 0.0f;
        const float* xr = xs + k * 260 + w * 32;
        #pragma unroll
        for (int d4 = 0; d4 < 8; d4++) {
            float4 xv = *reinterpret_cast<const float4*>(xr + d4 * 4);
            #pragma unroll
            for (int h = 0; h < 8; h++) {
                float4 qv = *reinterpret_cast<const float4*>(qts + h * 260 + w * 32 + d4 * 4);
                acc[h] = fmaf(qv.x, xv.x, fmaf(qv.y, xv.y,
                          fmaf(qv.z, xv.z, fmaf(qv.w, xv.w, acc[h]))));
            }
        }
        #pragma unroll
        for (int h = 0; h < 8; h++)
            sred[w * 256 + h * 32 + k] = acc[h];
    }
    __syncthreads();

    // ---- softmax: warp w handles head h=w, lane = k ----
    {
        int h = w, k = lane;
        float sc = 0.0f;
        #pragma unroll
        for (int ww = 0; ww < 8; ww++)
            sc += sred[ww * 256 + h * 32 + k];
        sc *= 0.17677669529663687f;   // 1/sqrt(32)
        float m = sc;
        #pragma unroll
        for (int o = 16; o; o >>= 1) m = fmaxf(m, __shfl_xor_sync(0xFFFFFFFFu, m, o));
        float e = expf(sc - m);
        float s = e;
        #pragma unroll
        for (int o = 16; o; o >>= 1) s += __shfl_xor_sync(0xFFFFFFFFu, s, o);
        attns[h * 32 + k] = e / s;
    }
    __syncthreads();

    // ---- phase 2: ctx; warp = (4-head group, d-quarter), lane = d-pair ----
    {
        int hg  = w >> 2;
        int dqt = w & 3;
        int dbase = dqt * 64 + lane * 2;
        float acc[4][2];
        #pragma unroll
        for (int h = 0; h < 4; h++) { acc[h][0] = 0.f; acc[h][1] = 0.f; }
        #pragma unroll
        for (int k0 = 0; k0 < 32; k0 += 4) {
            float4 a0 = *reinterpret_cast<const float4*>(&attns[(hg * 4 + 0) * 32 + k0]);
            float4 a1 = *reinterpret_cast<const float4*>(&attns[(hg * 4 + 1) * 32 + k0]);
            float4 a2 = *reinterpret_cast<const float4*>(&attns[(hg * 4 + 2) * 32 + k0]);
            float4 a3 = *reinterpret_cast<const float4*>(&attns[(hg * 4 + 3) * 32 + k0]);
            float av0[4] = {a0.x, a0.y, a0.z, a0.w};
            float av1[4] = {a1.x, a1.y, a1.z, a1.w};
            float av2[4] = {a2.x, a2.y, a2.z, a2.w};
            float av3[4] = {a3.x, a3.y, a3.z, a3.w};
            #pragma unroll
            for (int kk = 0; kk < 4; kk++) {
                float2 xv = *reinterpret_cast<const float2*>(xs + (k0 + kk) * 260 + dbase);
                acc[0][0] = fmaf(av0[kk], xv.x, acc[0][0]);
                acc[0][1] = fmaf(av0[kk], xv.y, acc[0][1]);
                acc[1][0] = fmaf(av1[kk], xv.x, acc[1][0]);
                acc[1][1] = fmaf(av1[kk], xv.y, acc[1][1]);
                acc[2][0] = fmaf(av2[kk], xv.x, acc[2][0]);
                acc[2][1] = fmaf(av2[kk], xv.y, acc[2][1]);
                acc[3][0] = fmaf(av3[kk], xv.x, acc[3][0]);
                acc[3][1] = fmaf(av3[kk], xv.y, acc[3][1]);
            }
        }
        float* cb = ctx + (size_t)b * 2048;
        #pragma unroll
        for (int h = 0; h < 4; h++) {
            *reinterpret_cast<float2*>(cb + (hg * 4 + h) * 256 + dbase) =
                make_float2(acc[h][0], acc[h][1]);
        }
    }
}

// ---------------- out[b, h*32+j] = sum_d ctx[b,h,d] * W_v[d, h*32+j] ----------------
__global__ void vproj_kernel(const float* __restrict__ ctx, const float* __restrict__ Wv,
                             float* __restrict__ out) {
    __shared__ float Wvs[256 * 32];
    __shared__ float cs[16 * 256];
    int h  = blockIdx.y;
    int b0 = blockIdx.x * 16;
    int tid = threadIdx.x;
    for (int i = tid * 4; i < 8192; i += 1024) {
        int d = i >> 5, j = i & 31;
        *reinterpret_cast<float4*>(&Wvs[i]) =
            *reinterpret_cast<const float4*>(&Wv[d * 256 + h * 32 + j]);
    }
    for (int i = tid * 4; i < 4096; i += 1024) {
        int r = i >> 8, d2 = i & 255;
        *reinterpret_cast<float4*>(&cs[i]) =
            *reinterpret_cast<const float4*>(&ctx[(size_t)(b0 + r) * 2048 + h * 256 + d2]);
    }
    __syncthreads();
    int j  = tid & 31;
    int rg = tid >> 5;
    float acc0 = 0.0f, acc1 = 0.0f;
    #pragma unroll 4
    for (int d4 = 0; d4 < 64; d4++) {
        float w0 = Wvs[(d4 * 4 + 0) * 32 + j];
        float w1 = Wvs[(d4 * 4 + 1) * 32 + j];
        float w2 = Wvs[(d4 * 4 + 2) * 32 + j];
        float w3 = Wvs[(d4 * 4 + 3) * 32 + j];
        float4 c0 = *reinterpret_cast<const float4*>(&cs[rg * 256 + d4 * 4]);
        float4 c1 = *reinterpret_cast<const float4*>(&cs[(rg + 8) * 256 + d4 * 4]);
        acc0 += c0.x * w0 + c0.y * w1 + c0.z * w2 + c0.w * w3;
        acc1 += c1.x * w0 + c1.y * w1 + c1.z * w2 + c1.w * w3;
    }
    out[(size_t)(b0 + rg) * 256 + h * 32 + j]     = acc0;
    out[(size_t)(b0 + rg + 8) * 256 + h * 32 + j] = acc1;
}

// ---------------- launcher ----------------
extern "C" void kernel_launch(void* const* d_in, const int* in_sizes, int n_in,
                              void* d_out, int out_size) {
    const float* x_anc = (const float*)d_in[0];
    const float* x_nei = (const float*)d_in[1];
    const float* W_q   = (const float*)d_in[2];
    const float* W_k   = (const float*)d_in[3];
    const float* W_v   = (const float*)d_in[4];
    const float* W_o   = (const float*)d_in[5];
    const float* ln1_g = (const float*)d_in[6];
    const float* ln1_b = (const float*)d_in[7];
    const float* ln2_g = (const float*)d_in[8];
    const float* ln2_b = (const float*)d_in[9];
    const float* ff1_w = (const float*)d_in[10];
    const float* ff1_b = (const float*)d_in[11];
    const float* ff2_w = (const float*)d_in[12];
    const float* ff2_b = (const float*)d_in[13];
    float* out = (float*)d_out;

    float *p_lnx, *p_q, *p_qt, *p_ctx, *p_att, *p_x, *p_h, *p_ff;
    cudaGetSymbolAddress((void**)&p_lnx, g_lnx);
    cudaGetSymbolAddress((void**)&p_q,   g_q);
    cudaGetSymbolAddress((void**)&p_qt,  g_qt);
    cudaGetSymbolAddress((void**)&p_ctx, g_ctx);
    cudaGetSymbolAddress((void**)&p_att, g_att);
    cudaGetSymbolAddress((void**)&p_x,   g_x);
    cudaGetSymbolAddress((void**)&p_h,   g_h);
    cudaGetSymbolAddress((void**)&p_ff,  g_ff);

    dim3 lnBlock(32, 8);

    // 1. LN1
    ln_kernel<<<BN / 8, lnBlock>>>(x_anc, ln1_g, ln1_b, p_lnx);
    // 2. Q = LN1 @ W_q  (tf32 tensor cores)
    tgemm<0><<<dim3(DIM / 128, BN / 128), 256>>>(p_lnx, W_q, p_q, BN, DIM, DIM, nullptr, nullptr);
    // 3. q~ per head
    qtilde_kernel<<<dim3(BN / 8, NH), 256>>>(p_q, W_k, p_qt);
    // 4. attention core -> ctx
    attn_kernel<<<BN, 256>>>(x_nei, p_qt, p_ctx);
    // 5. out = ctx @ W_v (per head)
    vproj_kernel<<<dim3(BN / 16, NH), 256>>>(p_ctx, W_v, p_att);
    // 6. x = x_anc + att @ W_o
    tgemm<3><<<dim3(DIM / 128, BN / 128), 256>>>(p_att, W_o, p_x, BN, DIM, DIM, nullptr, x_anc);
    // 7. LN2
    ln_kernel<<<BN / 8, lnBlock>>>(p_x, ln2_g, ln2_b, p_h);
    // 8. ff = gelu(h @ ff1 + b1)
    tgemm<1><<<dim3(NFF / 128, BN / 128), 256>>>(p_h, ff1_w, p_ff, BN, NFF, DIM, ff1_b, nullptr);
    // 9. out = x + ff @ ff2 + b2
    tgemm<2><<<dim3(DIM / 128, BN / 128), 256>>>(p_ff, ff2_w, out, BN, DIM, NFF, ff2_b, p_x);
}